// round 5
// baseline (speedup 1.0000x reference)
#include <cuda_runtime.h>

#define N_NODES 50000
#define N_EDGES 800000
#define EMB 128
#define EDGE_DIM 64
#define IN_DIM 64
#define OUT_DIM 32

// Scratch (allocation-free rule: __device__ globals)
__device__ float g_h[(size_t)N_NODES * EMB];      // node embeddings (in-place updated)
__device__ float g_aggr[(size_t)N_NODES * EMB];   // scatter-sum accumulator
__device__ float g_e[(size_t)N_EDGES * EDGE_DIM]; // edge features (in-place updated)
__device__ int   g_src[N_EDGES];
__device__ int   g_dst[N_EDGES];
__device__ int   g_is64;

static inline int imin_host(int a, int b) { return a < b ? a : b; }

// Detect whether edge_index is int64 or int32.
// int64 layout: [lo0, hi0, lo1, hi1, ...] with hi == 0 (indices in [0, 50000)).
// int32 layout: odd words are real random indices -> some nonzero.
__global__ void detect_kernel(const unsigned int* __restrict__ w) {
    __shared__ int any;
    if (threadIdx.x == 0) any = 0;
    __syncthreads();
    for (int i = threadIdx.x; i < 4096; i += blockDim.x)
        if (w[2 * i + 1] != 0u) any = 1;   // benign race: only sets 1
    __syncthreads();
    if (threadIdx.x == 0) g_is64 = any ? 0 : 1;
}

// Normalize to int32 and CLAMP into [0, N_NODES): converts any residual
// index-misread into a finite-rel_err correctness signal instead of an
// opaque illegal-memory-access fault. No-op when indices are read right.
__global__ void convert_kernel(const void* __restrict__ ei) {
    int i = blockIdx.x * blockDim.x + threadIdx.x;
    const int stride = gridDim.x * blockDim.x;
    const int is64 = g_is64;
    for (; i < 2 * N_EDGES; i += stride) {
        int v;
        if (is64) v = (int)((const long long*)ei)[i];
        else      v = ((const int*)ei)[i];
        v = min(max(v, 0), N_NODES - 1);
        if (i < N_EDGES) g_src[i] = v; else g_dst[i - N_EDGES] = v;
    }
}

__global__ void zero_kernel(float4* __restrict__ p, int n4) {
    int i = blockIdx.x * blockDim.x + threadIdx.x;
    const int stride = gridDim.x * blockDim.x;
    const float4 z = make_float4(0.f, 0.f, 0.f, 0.f);
    for (; i < n4; i += stride) p[i] = z;
}

// Generic gathered GEMM:
//   Out[r, :] (or atomicAdd into Out[OI[r], :]) =
//     act( concat(A0[I0[r]], A1[I1[r]], A2[I2[r]]) @ W + bias )
// Row tile = 128, col tile = TILE_N (full output width).
// SMEM: Ws [K x TILE_N] resident, As [ws x 128] per-segment staging (k-major).
template <int TILE_N>
__global__ __launch_bounds__(256) void gemm_gather(
    int M,
    const float* __restrict__ A0, const int* __restrict__ I0, int w0,
    const float* __restrict__ A1, const int* __restrict__ I1, int w1,
    const float* __restrict__ A2, const int* __restrict__ I2, int w2,
    const float* __restrict__ W, const float* __restrict__ bias,
    float* __restrict__ Out, const int* __restrict__ OI, int relu)
{
    constexpr int TN = TILE_N / 16;   // per-thread cols (16 col-groups)
    extern __shared__ float smem[];
    const int K = w0 + w1 + w2;
    float* Ws = smem;                 // K * TILE_N
    float* As = smem + K * TILE_N;    // up to 128 * 128

    const int tid = threadIdx.x;

    // Cooperative W load
    for (int i = tid * 4; i < K * TILE_N; i += 1024)
        *(float4*)&Ws[i] = *(const float4*)&W[i];

    const int tx = tid & 15;   // col group
    const int ty = tid >> 4;   // row group (8 rows each)

    float bv[TN];
#pragma unroll
    for (int j = 0; j < TN; ++j) bv[j] = bias[tx * TN + j];

    const int ntiles = (M + 127) >> 7;
    for (int tile = blockIdx.x; tile < ntiles; tile += gridDim.x) {
        const int row0 = tile << 7;
        const int rows = min(128, M - row0);

        float acc[8][TN];
#pragma unroll
        for (int i = 0; i < 8; ++i)
#pragma unroll
            for (int j = 0; j < TN; ++j) acc[i][j] = 0.f;

        int kbase = 0;
#pragma unroll
        for (int seg = 0; seg < 3; ++seg) {
            const float* A = (seg == 0) ? A0 : ((seg == 1) ? A1 : A2);
            const int* I   = (seg == 0) ? I0 : ((seg == 1) ? I1 : I2);
            const int ws   = (seg == 0) ? w0 : ((seg == 1) ? w1 : w2);
            if (ws == 0) continue;

            __syncthreads();  // protect As from previous use
            {
                // Gather segment rows into As[k][m] (transpose during load).
                const int m = tid & 127;
                const float* rp = nullptr;
                if (m < rows) {
                    const int gm = row0 + m;
                    const long long r = I ? (long long)I[gm] : (long long)gm;
                    rp = A + r * (long long)ws;
                }
                for (int k4 = tid >> 7; k4 < (ws >> 2); k4 += 2) {
                    float4 v = rp ? *(const float4*)(rp + k4 * 4)
                                  : make_float4(0.f, 0.f, 0.f, 0.f);
                    As[(k4 * 4 + 0) * 128 + m] = v.x;
                    As[(k4 * 4 + 1) * 128 + m] = v.y;
                    As[(k4 * 4 + 2) * 128 + m] = v.z;
                    As[(k4 * 4 + 3) * 128 + m] = v.w;
                }
            }
            __syncthreads();

            const float* wsp = Ws + kbase * TILE_N + tx * TN;
            const float* asp = As + ty * 8;
#pragma unroll 2
            for (int k = 0; k < ws; ++k) {
                float4 a0 = *(const float4*)(asp + k * 128);
                float4 a1 = *(const float4*)(asp + k * 128 + 4);
                float av[8] = {a0.x, a0.y, a0.z, a0.w, a1.x, a1.y, a1.z, a1.w};
                float wv[TN];
                if constexpr (TN == 8) {
                    float4 b0 = *(const float4*)(wsp + k * TILE_N);
                    float4 b1 = *(const float4*)(wsp + k * TILE_N + 4);
                    wv[0] = b0.x; wv[1] = b0.y; wv[2] = b0.z; wv[3] = b0.w;
                    wv[4] = b1.x; wv[5] = b1.y; wv[6] = b1.z; wv[7] = b1.w;
                } else if constexpr (TN == 4) {
                    float4 b0 = *(const float4*)(wsp + k * TILE_N);
                    wv[0] = b0.x; wv[1] = b0.y; wv[2] = b0.z; wv[3] = b0.w;
                } else {
                    float2 b0 = *(const float2*)(wsp + k * TILE_N);
                    wv[0] = b0.x; wv[1] = b0.y;
                }
#pragma unroll
                for (int i = 0; i < 8; ++i)
#pragma unroll
                    for (int j = 0; j < TN; ++j)
                        acc[i][j] = fmaf(av[i], wv[j], acc[i][j]);
            }
            kbase += ws;
        }

        // Epilogue: bias (+relu), then direct store or atomic scatter-add.
#pragma unroll
        for (int i = 0; i < 8; ++i) {
            const int m = ty * 8 + i;
            if (m < rows) {
                const int gm = row0 + m;
                if (OI) {
                    float* op = Out + (long long)OI[gm] * TILE_N + tx * TN;
#pragma unroll
                    for (int j = 0; j < TN; ++j) {
                        float v = acc[i][j] + bv[j];
                        if (relu) v = fmaxf(v, 0.f);
                        atomicAdd(op + j, v);
                    }
                } else {
                    float* op = Out + (long long)gm * TILE_N + tx * TN;
#pragma unroll
                    for (int j = 0; j < TN; ++j) {
                        float v = acc[i][j] + bv[j];
                        if (relu) v = fmaxf(v, 0.f);
                        op[j] = v;
                    }
                }
            }
        }
    }
}

__device__ __forceinline__ float dot4(float4 a, float4 b) {
    return a.x * b.x + a.y * b.y + a.z * b.z + a.w * b.w;
}

// edge_pred[e] = h[src]·W[0:128] + h[dst]·W[128:256] + e·W[256:320] + b
__global__ __launch_bounds__(256) void edge_pred_kernel(
    const float* __restrict__ h, const float* __restrict__ e,
    const int* __restrict__ src, const int* __restrict__ dst,
    const float* __restrict__ W, const float* __restrict__ b,
    float* __restrict__ out, int E)
{
    const int warp = (blockIdx.x * blockDim.x + threadIdx.x) >> 5;
    const int lane = threadIdx.x & 31;
    if (warp >= E) return;
    const int s = src[warp];
    const int d = dst[warp];
    const float4* W4 = (const float4*)W;
    float acc = dot4(((const float4*)(h + (long long)s * EMB))[lane], W4[lane]);
    acc += dot4(((const float4*)(h + (long long)d * EMB))[lane], W4[32 + lane]);
    if (lane < 16)
        acc += dot4(((const float4*)(e + (long long)warp * EDGE_DIM))[lane],
                    W4[64 + lane]);
#pragma unroll
    for (int off = 16; off; off >>= 1)
        acc += __shfl_down_sync(0xffffffffu, acc, off);
    if (lane == 0) out[warp] = acc + b[0];
}

extern "C" void kernel_launch(void* const* d_in, const int* in_sizes, int n_in,
                              void* d_out, int out_size)
{
    const float* x          = (const float*)d_in[0];
    const float* edge_attr  = (const float*)d_in[1];
    const void*  ei         = (const void*)d_in[2];
    const float* emb_W      = (const float*)d_in[3];
    const float* emb_b      = (const float*)d_in[4];
    const float* msg_W      = (const float*)d_in[5];
    const float* msg_b      = (const float*)d_in[6];
    const float* upd_W      = (const float*)d_in[7];
    const float* upd_b      = (const float*)d_in[8];
    const float* eupd_W     = (const float*)d_in[9];
    const float* eupd_b     = (const float*)d_in[10];
    const float* npred_W    = (const float*)d_in[11];
    const float* npred_b    = (const float*)d_in[12];
    const float* epred_W    = (const float*)d_in[13];
    const float* epred_b    = (const float*)d_in[14];
    float* out = (float*)d_out;

    float *h = nullptr, *aggr = nullptr, *ebuf = nullptr;
    int *src = nullptr, *dst = nullptr;
    cudaGetSymbolAddress((void**)&h, g_h);
    cudaGetSymbolAddress((void**)&aggr, g_aggr);
    cudaGetSymbolAddress((void**)&ebuf, g_e);
    cudaGetSymbolAddress((void**)&src, g_src);
    cudaGetSymbolAddress((void**)&dst, g_dst);

    int nsm = 148;
    cudaDeviceGetAttribute(&nsm, cudaDevAttrMultiProcessorCount, 0);

    cudaFuncSetAttribute(gemm_gather<128>,
                         cudaFuncAttributeMaxDynamicSharedMemorySize, 196608);
    cudaFuncSetAttribute(gemm_gather<64>,
                         cudaFuncAttributeMaxDynamicSharedMemorySize, 147456);
    cudaFuncSetAttribute(gemm_gather<32>,
                         cudaFuncAttributeMaxDynamicSharedMemorySize, 81920);

    // Normalize edge_index (int32 or int64) into int32 g_src/g_dst.
    detect_kernel<<<1, 256>>>((const unsigned int*)ei);
    convert_kernel<<<nsm * 4, 256>>>(ei);

    const int nt_n = (N_NODES + 127) / 128;  // 391 node tiles

    // h = x @ emb_W + emb_b   (no relu)
    gemm_gather<128><<<imin_host(nt_n, 2 * nsm), 256,
                       (IN_DIM * 128 + IN_DIM * 128) * 4>>>(
        N_NODES, x, nullptr, IN_DIM, nullptr, nullptr, 0, nullptr, nullptr, 0,
        emb_W, emb_b, h, nullptr, 0);

    for (int l = 0; l < 2; ++l) {
        const float* e_in = (l == 0) ? edge_attr : ebuf;

        zero_kernel<<<nsm * 4, 256>>>((float4*)aggr, N_NODES * EMB / 4);

        // fused message + scatter-sum:
        // aggr[dst] += relu([h[src], e] @ msg_W + msg_b)
        gemm_gather<128><<<nsm, 256, (192 * 128 + 128 * 128) * 4>>>(
            N_EDGES, h, src, EMB, e_in, nullptr, EDGE_DIM, nullptr, nullptr, 0,
            msg_W + l * 192 * 128, msg_b + l * 128, aggr, dst, 1);

        // h = relu([aggr, h] @ upd_W + upd_b)   (in-place safe: per-row dep)
        gemm_gather<128><<<nsm, 256, (256 * 128 + 128 * 128) * 4>>>(
            N_NODES, aggr, nullptr, EMB, h, nullptr, EMB, nullptr, nullptr, 0,
            upd_W + l * 256 * 128, upd_b + l * 128, h, nullptr, 1);

        // e = relu([h[src], h[dst], e] @ eupd_W + eupd_b)  (in-place safe)
        gemm_gather<64><<<nsm, 256, (320 * 64 + 128 * 128) * 4>>>(
            N_EDGES, h, src, EMB, h, dst, EMB, e_in, nullptr, EDGE_DIM,
            eupd_W + l * 320 * 64, eupd_b + l * 64, ebuf, nullptr, 1);
    }

    // node_pred = h @ npred_W + npred_b
    gemm_gather<32><<<imin_host(nt_n, 2 * nsm), 256,
                      (128 * 32 + 128 * 128) * 4>>>(
        N_NODES, h, nullptr, EMB, nullptr, nullptr, 0, nullptr, nullptr, 0,
        npred_W, npred_b, out, nullptr, 0);

    // edge_pred
    edge_pred_kernel<<<(N_EDGES + 7) / 8, 256>>>(
        h, ebuf, src, dst, epred_W, epred_b,
        out + (long long)N_NODES * OUT_DIM, N_EDGES);
}

// round 7
// speedup vs baseline: 1.0231x; 1.0231x over previous
#include <cuda_runtime.h>

#define N_NODES 50000
#define N_EDGES 800000
#define EMB 128
#define EDGE_DIM 64
#define IN_DIM 64
#define OUT_DIM 32

typedef unsigned long long u64;

// Scratch (allocation-free rule: __device__ globals)
__device__ float g_h[(size_t)N_NODES * EMB];
__device__ float g_aggr[(size_t)N_NODES * EMB];
__device__ float g_e[(size_t)N_EDGES * EDGE_DIM];
__device__ int   g_src[N_EDGES];
__device__ int   g_dst[N_EDGES];
__device__ int   g_is64;

static inline int imin_host(int a, int b) { return a < b ? a : b; }

// ---- packed f32x2 helpers (sm_103a FFMA2 path) ----
__device__ __forceinline__ u64 dup2(float v) {
    u64 r; asm("mov.b64 %0, {%1, %1};" : "=l"(r) : "f"(v)); return r;
}
__device__ __forceinline__ void ffma2(u64& d, u64 a, u64 b) {
    asm("fma.rn.f32x2 %0, %1, %2, %3;" : "=l"(d) : "l"(a), "l"(b), "l"(d));
}
__device__ __forceinline__ float2 unpack2(u64 v) {
    float2 f; asm("mov.b64 {%0, %1}, %2;" : "=f"(f.x), "=f"(f.y) : "l"(v));
    return f;
}

// Detect whether edge_index is int64 or int32 (odd 32-bit words all zero <=> int64).
__global__ void detect_kernel(const unsigned int* __restrict__ w) {
    __shared__ int any;
    if (threadIdx.x == 0) any = 0;
    __syncthreads();
    for (int i = threadIdx.x; i < 4096; i += blockDim.x)
        if (w[2 * i + 1] != 0u) any = 1;
    __syncthreads();
    if (threadIdx.x == 0) g_is64 = any ? 0 : 1;
}

// Normalize to int32, clamped into [0, N_NODES).
__global__ void convert_kernel(const void* __restrict__ ei) {
    int i = blockIdx.x * blockDim.x + threadIdx.x;
    const int stride = gridDim.x * blockDim.x;
    const int is64 = g_is64;
    for (; i < 2 * N_EDGES; i += stride) {
        int v;
        if (is64) v = (int)((const long long*)ei)[i];
        else      v = ((const int*)ei)[i];
        v = min(max(v, 0), N_NODES - 1);
        if (i < N_EDGES) g_src[i] = v; else g_dst[i - N_EDGES] = v;
    }
}

__global__ void zero_kernel(float4* __restrict__ p, int n4) {
    int i = blockIdx.x * blockDim.x + threadIdx.x;
    const int stride = gridDim.x * blockDim.x;
    const float4 z = make_float4(0.f, 0.f, 0.f, 0.f);
    for (; i < n4; i += stride) p[i] = z;
}

// Generic gathered GEMM with packed-f32x2 mainloop:
//   Out[r, :] (or atomicAdd into Out[OI[r], :]) =
//     act( concat(A0[I0[r]], A1[I1[r]], A2[I2[r]]) @ W + bias )
// Row tile = 128, col tile = TILE_N (full output width).
// acc packed along rows: acc2[i2][j] holds rows (ty*8+2*i2, +1), col tx*TN+j.
template <int TILE_N>
__global__ __launch_bounds__(256) void gemm_gather(
    int M,
    const float* __restrict__ A0, const int* __restrict__ I0, int w0,
    const float* __restrict__ A1, const int* __restrict__ I1, int w1,
    const float* __restrict__ A2, const int* __restrict__ I2, int w2,
    const float* __restrict__ W, const float* __restrict__ bias,
    float* __restrict__ Out, const int* __restrict__ OI, int relu)
{
    constexpr int TN = TILE_N / 16;   // per-thread cols (16 col-groups)
    extern __shared__ float smem[];
    const int K = w0 + w1 + w2;
    float* Ws = smem;                 // K * TILE_N
    float* As = smem + K * TILE_N;    // up to 128 * 128

    const int tid = threadIdx.x;

    // Cooperative W load
    for (int i = tid * 4; i < K * TILE_N; i += 1024)
        *(float4*)&Ws[i] = *(const float4*)&W[i];

    const int tx = tid & 15;   // col group
    const int ty = tid >> 4;   // row group (8 rows each)

    float bv[TN];
#pragma unroll
    for (int j = 0; j < TN; ++j) bv[j] = bias[tx * TN + j];

    const int ntiles = (M + 127) >> 7;
    for (int tile = blockIdx.x; tile < ntiles; tile += gridDim.x) {
        const int row0 = tile << 7;
        const int rows = min(128, M - row0);

        u64 acc2[4][TN];
#pragma unroll
        for (int i = 0; i < 4; ++i)
#pragma unroll
            for (int j = 0; j < TN; ++j) acc2[i][j] = 0ull;

        int kbase = 0;
#pragma unroll
        for (int seg = 0; seg < 3; ++seg) {
            const float* A = (seg == 0) ? A0 : ((seg == 1) ? A1 : A2);
            const int* I   = (seg == 0) ? I0 : ((seg == 1) ? I1 : I2);
            const int ws   = (seg == 0) ? w0 : ((seg == 1) ? w1 : w2);
            if (ws == 0) continue;

            __syncthreads();  // protect As from previous use
            {
                // Gather segment rows into As[k][m] (transpose during load).
                const int m = tid & 127;
                const float* rp = nullptr;
                if (m < rows) {
                    const int gm = row0 + m;
                    const long long r = I ? (long long)I[gm] : (long long)gm;
                    rp = A + r * (long long)ws;
                }
                for (int k4 = tid >> 7; k4 < (ws >> 2); k4 += 2) {
                    float4 v = rp ? *(const float4*)(rp + k4 * 4)
                                  : make_float4(0.f, 0.f, 0.f, 0.f);
                    As[(k4 * 4 + 0) * 128 + m] = v.x;
                    As[(k4 * 4 + 1) * 128 + m] = v.y;
                    As[(k4 * 4 + 2) * 128 + m] = v.z;
                    As[(k4 * 4 + 3) * 128 + m] = v.w;
                }
            }
            __syncthreads();

            const float* wsp = Ws + kbase * TILE_N + tx * TN;
            const float* asp = As + ty * 8;
#pragma unroll 2
            for (int k = 0; k < ws; ++k) {
                // A side: 8 rows = 4 ready-packed f32x2 pairs (no movs).
                const float* a_ptr = asp + k * 128;
                ulonglong2 p0 = *(const ulonglong2*)a_ptr;
                ulonglong2 p1 = *(const ulonglong2*)(a_ptr + 4);
                u64 av2[4] = {p0.x, p0.y, p1.x, p1.y};

                // W side: TN scalars, each duplicated into both halves.
                const float* w_ptr = wsp + k * TILE_N;
                u64 wd[TN];
                if constexpr (TN == 8) {
                    float4 b0 = *(const float4*)w_ptr;
                    float4 b1 = *(const float4*)(w_ptr + 4);
                    wd[0] = dup2(b0.x); wd[1] = dup2(b0.y);
                    wd[2] = dup2(b0.z); wd[3] = dup2(b0.w);
                    wd[4] = dup2(b1.x); wd[5] = dup2(b1.y);
                    wd[6] = dup2(b1.z); wd[7] = dup2(b1.w);
                } else if constexpr (TN == 4) {
                    float4 b0 = *(const float4*)w_ptr;
                    wd[0] = dup2(b0.x); wd[1] = dup2(b0.y);
                    wd[2] = dup2(b0.z); wd[3] = dup2(b0.w);
                } else {
                    float2 b0 = *(const float2*)w_ptr;
                    wd[0] = dup2(b0.x); wd[1] = dup2(b0.y);
                }
#pragma unroll
                for (int i = 0; i < 4; ++i)
#pragma unroll
                    for (int j = 0; j < TN; ++j)
                        ffma2(acc2[i][j], av2[i], wd[j]);
            }
            kbase += ws;
        }

        // Epilogue: unpack row pairs, bias (+relu), store / scatter-add.
#pragma unroll
        for (int i2 = 0; i2 < 4; ++i2) {
            float vlo[TN], vhi[TN];
#pragma unroll
            for (int j = 0; j < TN; ++j) {
                float2 p = unpack2(acc2[i2][j]);
                vlo[j] = p.x + bv[j];
                vhi[j] = p.y + bv[j];
                if (relu) { vlo[j] = fmaxf(vlo[j], 0.f); vhi[j] = fmaxf(vhi[j], 0.f); }
            }
            const int m0 = ty * 8 + 2 * i2;
#pragma unroll
            for (int half = 0; half < 2; ++half) {
                const int m = m0 + half;
                const float* v = half ? vhi : vlo;
                if (m >= rows) continue;
                const int gm = row0 + m;
                if (OI) {
                    float* op = Out + (long long)OI[gm] * TILE_N + tx * TN;
#pragma unroll
                    for (int j = 0; j < TN; ++j) atomicAdd(op + j, v[j]);
                } else {
                    float* op = Out + (long long)gm * TILE_N + tx * TN;
                    if constexpr (TN == 8) {
                        *(float4*)op       = make_float4(v[0], v[1], v[2], v[3]);
                        *(float4*)(op + 4) = make_float4(v[4], v[5], v[6], v[7]);
                    } else if constexpr (TN == 4) {
                        *(float4*)op = make_float4(v[0], v[1], v[2], v[3]);
                    } else {
                        *(float2*)op = make_float2(v[0], v[1]);
                    }
                }
            }
        }
    }
}

__device__ __forceinline__ float dot4(float4 a, float4 b) {
    return a.x * b.x + a.y * b.y + a.z * b.z + a.w * b.w;
}

// edge_pred[e] = h[src]·W[0:128] + h[dst]·W[128:256] + e·W[256:320] + b
__global__ __launch_bounds__(256) void edge_pred_kernel(
    const float* __restrict__ h, const float* __restrict__ e,
    const int* __restrict__ src, const int* __restrict__ dst,
    const float* __restrict__ W, const float* __restrict__ b,
    float* __restrict__ out, int E)
{
    const int warp = (blockIdx.x * blockDim.x + threadIdx.x) >> 5;
    const int lane = threadIdx.x & 31;
    if (warp >= E) return;
    const int s = src[warp];
    const int d = dst[warp];
    const float4* W4 = (const float4*)W;
    float acc = dot4(((const float4*)(h + (long long)s * EMB))[lane], W4[lane]);
    acc += dot4(((const float4*)(h + (long long)d * EMB))[lane], W4[32 + lane]);
    if (lane < 16)
        acc += dot4(((const float4*)(e + (long long)warp * EDGE_DIM))[lane],
                    W4[64 + lane]);
#pragma unroll
    for (int off = 16; off; off >>= 1)
        acc += __shfl_down_sync(0xffffffffu, acc, off);
    if (lane == 0) out[warp] = acc + b[0];
}

extern "C" void kernel_launch(void* const* d_in, const int* in_sizes, int n_in,
                              void* d_out, int out_size)
{
    const float* x          = (const float*)d_in[0];
    const float* edge_attr  = (const float*)d_in[1];
    const void*  ei         = (const void*)d_in[2];
    const float* emb_W      = (const float*)d_in[3];
    const float* emb_b      = (const float*)d_in[4];
    const float* msg_W      = (const float*)d_in[5];
    const float* msg_b      = (const float*)d_in[6];
    const float* upd_W      = (const float*)d_in[7];
    const float* upd_b      = (const float*)d_in[8];
    const float* eupd_W     = (const float*)d_in[9];
    const float* eupd_b     = (const float*)d_in[10];
    const float* npred_W    = (const float*)d_in[11];
    const float* npred_b    = (const float*)d_in[12];
    const float* epred_W    = (const float*)d_in[13];
    const float* epred_b    = (const float*)d_in[14];
    float* out = (float*)d_out;

    float *h = nullptr, *aggr = nullptr, *ebuf = nullptr;
    int *src = nullptr, *dst = nullptr;
    cudaGetSymbolAddress((void**)&h, g_h);
    cudaGetSymbolAddress((void**)&aggr, g_aggr);
    cudaGetSymbolAddress((void**)&ebuf, g_e);
    cudaGetSymbolAddress((void**)&src, g_src);
    cudaGetSymbolAddress((void**)&dst, g_dst);

    int nsm = 148;
    cudaDeviceGetAttribute(&nsm, cudaDevAttrMultiProcessorCount, 0);

    cudaFuncSetAttribute(gemm_gather<128>,
                         cudaFuncAttributeMaxDynamicSharedMemorySize, 196608);
    cudaFuncSetAttribute(gemm_gather<64>,
                         cudaFuncAttributeMaxDynamicSharedMemorySize, 147456);
    cudaFuncSetAttribute(gemm_gather<32>,
                         cudaFuncAttributeMaxDynamicSharedMemorySize, 81920);

    // Normalize edge_index (int32 or int64) into int32 g_src/g_dst.
    detect_kernel<<<1, 256>>>((const unsigned int*)ei);
    convert_kernel<<<nsm * 4, 256>>>(ei);

    const int nt_n = (N_NODES + 127) / 128;  // 391 node tiles

    // h = x @ emb_W + emb_b   (no relu)
    gemm_gather<128><<<imin_host(nt_n, 2 * nsm), 256,
                       (IN_DIM * 128 + IN_DIM * 128) * 4>>>(
        N_NODES, x, nullptr, IN_DIM, nullptr, nullptr, 0, nullptr, nullptr, 0,
        emb_W, emb_b, h, nullptr, 0);

    for (int l = 0; l < 2; ++l) {
        const float* e_in = (l == 0) ? edge_attr : ebuf;

        zero_kernel<<<nsm * 4, 256>>>((float4*)aggr, N_NODES * EMB / 4);

        // fused message + scatter-sum:
        // aggr[dst] += relu([h[src], e] @ msg_W + msg_b)
        gemm_gather<128><<<nsm, 256, (192 * 128 + 128 * 128) * 4>>>(
            N_EDGES, h, src, EMB, e_in, nullptr, EDGE_DIM, nullptr, nullptr, 0,
            msg_W + l * 192 * 128, msg_b + l * 128, aggr, dst, 1);

        // h = relu([aggr, h] @ upd_W + upd_b)   (in-place safe: per-row dep)
        gemm_gather<128><<<nsm, 256, (256 * 128 + 128 * 128) * 4>>>(
            N_NODES, aggr, nullptr, EMB, h, nullptr, EMB, nullptr, nullptr, 0,
            upd_W + l * 256 * 128, upd_b + l * 128, h, nullptr, 1);

        // e = relu([h[src], h[dst], e] @ eupd_W + eupd_b)  (in-place safe)
        gemm_gather<64><<<nsm, 256, (320 * 64 + 128 * 128) * 4>>>(
            N_EDGES, h, src, EMB, h, dst, EMB, e_in, nullptr, EDGE_DIM,
            eupd_W + l * 320 * 64, eupd_b + l * 64, ebuf, nullptr, 1);
    }

    // node_pred = h @ npred_W + npred_b
    gemm_gather<32><<<imin_host(nt_n, 2 * nsm), 256,
                      (128 * 32 + 128 * 128) * 4>>>(
        N_NODES, h, nullptr, EMB, nullptr, nullptr, 0, nullptr, nullptr, 0,
        npred_W, npred_b, out, nullptr, 0);

    // edge_pred
    edge_pred_kernel<<<(N_EDGES + 7) / 8, 256>>>(
        h, ebuf, src, dst, epred_W, epred_b,
        out + (long long)N_NODES * OUT_DIM, N_EDGES);
}

// round 9
// speedup vs baseline: 1.2341x; 1.2062x over previous
#include <cuda_runtime.h>

#define N_NODES 50000
#define N_EDGES 800000
#define EMB 128
#define EDGE_DIM 64
#define IN_DIM 64
#define OUT_DIM 32

typedef unsigned long long u64;

// Scratch (allocation-free rule: __device__ globals)
__device__ float g_h[(size_t)N_NODES * EMB];
__device__ float g_aggr[(size_t)N_NODES * EMB];
__device__ float g_e[(size_t)N_EDGES * EDGE_DIM];
__device__ int   g_src[N_EDGES];
__device__ int   g_dst[N_EDGES];
__device__ int   g_is64;

static inline int imin_host(int a, int b) { return a < b ? a : b; }

// ---- packed f32x2 helpers (sm_103a FFMA2 path) ----
__device__ __forceinline__ u64 dup2(float v) {
    u64 r; asm("mov.b64 %0, {%1, %1};" : "=l"(r) : "f"(v)); return r;
}
__device__ __forceinline__ void ffma2(u64& d, u64 a, u64 b) {
    asm("fma.rn.f32x2 %0, %1, %2, %3;" : "=l"(d) : "l"(a), "l"(b), "l"(d));
}
__device__ __forceinline__ float2 unpack2(u64 v) {
    float2 f; asm("mov.b64 {%0, %1}, %2;" : "=f"(f.x), "=f"(f.y) : "l"(v));
    return f;
}

// ---- vectorized global reductions (sm_90+) ----
__device__ __forceinline__ void red_add_v4(float* p, float a, float b, float c, float d) {
    asm volatile("red.global.add.v4.f32 [%0], {%1, %2, %3, %4};"
                 :: "l"(p), "f"(a), "f"(b), "f"(c), "f"(d) : "memory");
}
__device__ __forceinline__ void red_add_v2(float* p, float a, float b) {
    asm volatile("red.global.add.v2.f32 [%0], {%1, %2};"
                 :: "l"(p), "f"(a), "f"(b) : "memory");
}

// Detect whether edge_index is int64 or int32 (odd 32-bit words all zero <=> int64).
__global__ void detect_kernel(const unsigned int* __restrict__ w) {
    __shared__ int any;
    if (threadIdx.x == 0) any = 0;
    __syncthreads();
    for (int i = threadIdx.x; i < 4096; i += blockDim.x)
        if (w[2 * i + 1] != 0u) any = 1;
    __syncthreads();
    if (threadIdx.x == 0) g_is64 = any ? 0 : 1;
}

// Normalize to int32, clamped into [0, N_NODES).
__global__ void convert_kernel(const void* __restrict__ ei) {
    int i = blockIdx.x * blockDim.x + threadIdx.x;
    const int stride = gridDim.x * blockDim.x;
    const int is64 = g_is64;
    for (; i < 2 * N_EDGES; i += stride) {
        int v;
        if (is64) v = (int)((const long long*)ei)[i];
        else      v = ((const int*)ei)[i];
        v = min(max(v, 0), N_NODES - 1);
        if (i < N_EDGES) g_src[i] = v; else g_dst[i - N_EDGES] = v;
    }
}

__global__ void zero_kernel(float4* __restrict__ p, int n4) {
    int i = blockIdx.x * blockDim.x + threadIdx.x;
    const int stride = gridDim.x * blockDim.x;
    const float4 z = make_float4(0.f, 0.f, 0.f, 0.f);
    for (; i < n4; i += stride) p[i] = z;
}

// Generic gathered GEMM, 512 threads (4 warps/SMSP for latency hiding),
// packed-f32x2 mainloop:
//   Out[r, :] (or red.add into Out[OI[r], :]) =
//     act( concat(A0[I0[r]], A1[I1[r]], A2[I2[r]]) @ W + bias )
// Row tile = 128. Col tiling: G col-groups of TN cols, R row-groups of RPT rows.
template <int TILE_N>
__global__ __launch_bounds__(512) void gemm_gather(
    int M,
    const float* __restrict__ A0, const int* __restrict__ I0, int w0,
    const float* __restrict__ A1, const int* __restrict__ I1, int w1,
    const float* __restrict__ A2, const int* __restrict__ I2, int w2,
    const float* __restrict__ W, const float* __restrict__ bias,
    float* __restrict__ Out, const int* __restrict__ OI, int relu)
{
    constexpr int TN    = (TILE_N == 32) ? 2 : 4;  // cols per thread
    constexpr int G     = TILE_N / TN;             // col groups: 32 / 16 / 16
    constexpr int R     = 512 / G;                 // row groups: 16 / 32 / 32
    constexpr int RPT   = 128 / R;                 // rows per thread: 8 / 4 / 4
    constexpr int NPAIR = RPT / 2;                 // packed row pairs

    extern __shared__ float smem[];
    const int K = w0 + w1 + w2;
    float* Ws = smem;                 // K * TILE_N
    float* As = smem + K * TILE_N;    // up to 128 * 128

    const int tid = threadIdx.x;

    // Cooperative W load
    for (int i = tid * 4; i < K * TILE_N; i += 2048)
        *(float4*)&Ws[i] = *(const float4*)&W[i];

    const int tx = tid % G;   // col group
    const int ty = tid / G;   // row group (RPT rows each)

    float bv[TN];
#pragma unroll
    for (int j = 0; j < TN; ++j) bv[j] = bias[tx * TN + j];

    const int ntiles = (M + 127) >> 7;
    for (int tile = blockIdx.x; tile < ntiles; tile += gridDim.x) {
        const int row0 = tile << 7;
        const int rows = min(128, M - row0);

        u64 acc2[NPAIR][TN];
#pragma unroll
        for (int i = 0; i < NPAIR; ++i)
#pragma unroll
            for (int j = 0; j < TN; ++j) acc2[i][j] = 0ull;

        int kbase = 0;
#pragma unroll
        for (int seg = 0; seg < 3; ++seg) {
            const float* A = (seg == 0) ? A0 : ((seg == 1) ? A1 : A2);
            const int* I   = (seg == 0) ? I0 : ((seg == 1) ? I1 : I2);
            const int ws   = (seg == 0) ? w0 : ((seg == 1) ? w1 : w2);
            if (ws == 0) continue;

            __syncthreads();  // protect As from previous use
            {
                // Gather segment rows into As[k][m] (transpose during load).
                const int m = tid & 127;
                const float* rp = nullptr;
                if (m < rows) {
                    const int gm = row0 + m;
                    const long long r = I ? (long long)I[gm] : (long long)gm;
                    rp = A + r * (long long)ws;
                }
                for (int k4 = tid >> 7; k4 < (ws >> 2); k4 += 4) {
                    float4 v = rp ? *(const float4*)(rp + k4 * 4)
                                  : make_float4(0.f, 0.f, 0.f, 0.f);
                    As[(k4 * 4 + 0) * 128 + m] = v.x;
                    As[(k4 * 4 + 1) * 128 + m] = v.y;
                    As[(k4 * 4 + 2) * 128 + m] = v.z;
                    As[(k4 * 4 + 3) * 128 + m] = v.w;
                }
            }
            __syncthreads();

            const float* wsp = Ws + kbase * TILE_N + tx * TN;
            const float* asp = As + ty * RPT;
#pragma unroll 2
            for (int k = 0; k < ws; ++k) {
                // A side: RPT rows = NPAIR ready-packed f32x2 pairs.
                const float* a_ptr = asp + k * 128;
                u64 av2[NPAIR];
                if constexpr (RPT == 8) {
                    ulonglong2 p0 = *(const ulonglong2*)a_ptr;
                    ulonglong2 p1 = *(const ulonglong2*)(a_ptr + 4);
                    av2[0] = p0.x; av2[1] = p0.y; av2[2] = p1.x; av2[3] = p1.y;
                } else {
                    ulonglong2 p0 = *(const ulonglong2*)a_ptr;
                    av2[0] = p0.x; av2[1] = p0.y;
                }

                // W side: TN scalars, each duplicated into both halves.
                const float* w_ptr = wsp + k * TILE_N;
                u64 wd[TN];
                if constexpr (TN == 4) {
                    float4 b0 = *(const float4*)w_ptr;
                    wd[0] = dup2(b0.x); wd[1] = dup2(b0.y);
                    wd[2] = dup2(b0.z); wd[3] = dup2(b0.w);
                } else {
                    float2 b0 = *(const float2*)w_ptr;
                    wd[0] = dup2(b0.x); wd[1] = dup2(b0.y);
                }
#pragma unroll
                for (int i = 0; i < NPAIR; ++i)
#pragma unroll
                    for (int j = 0; j < TN; ++j)
                        ffma2(acc2[i][j], av2[i], wd[j]);
            }
            kbase += ws;
        }

        // Epilogue: unpack row pairs, bias (+relu), store / vector scatter-add.
#pragma unroll
        for (int i2 = 0; i2 < NPAIR; ++i2) {
            float vlo[TN], vhi[TN];
#pragma unroll
            for (int j = 0; j < TN; ++j) {
                float2 p = unpack2(acc2[i2][j]);
                vlo[j] = p.x + bv[j];
                vhi[j] = p.y + bv[j];
                if (relu) { vlo[j] = fmaxf(vlo[j], 0.f); vhi[j] = fmaxf(vhi[j], 0.f); }
            }
            const int m0 = ty * RPT + 2 * i2;
#pragma unroll
            for (int half = 0; half < 2; ++half) {
                const int m = m0 + half;
                const float* v = half ? vhi : vlo;
                if (m >= rows) continue;
                const int gm = row0 + m;
                if (OI) {
                    float* op = Out + (long long)OI[gm] * TILE_N + tx * TN;
                    if constexpr (TN == 4) red_add_v4(op, v[0], v[1], v[2], v[3]);
                    else                   red_add_v2(op, v[0], v[1]);
                } else {
                    float* op = Out + (long long)gm * TILE_N + tx * TN;
                    if constexpr (TN == 4)
                        *(float4*)op = make_float4(v[0], v[1], v[2], v[3]);
                    else
                        *(float2*)op = make_float2(v[0], v[1]);
                }
            }
        }
    }
}

__device__ __forceinline__ float dot4(float4 a, float4 b) {
    return a.x * b.x + a.y * b.y + a.z * b.z + a.w * b.w;
}

// edge_pred[e] = h[src]·W[0:128] + h[dst]·W[128:256] + e·W[256:320] + b
__global__ __launch_bounds__(256) void edge_pred_kernel(
    const float* __restrict__ h, const float* __restrict__ e,
    const int* __restrict__ src, const int* __restrict__ dst,
    const float* __restrict__ W, const float* __restrict__ b,
    float* __restrict__ out, int E)
{
    const int warp = (blockIdx.x * blockDim.x + threadIdx.x) >> 5;
    const int lane = threadIdx.x & 31;
    if (warp >= E) return;
    const int s = src[warp];
    const int d = dst[warp];
    const float4* W4 = (const float4*)W;
    float acc = dot4(((const float4*)(h + (long long)s * EMB))[lane], W4[lane]);
    acc += dot4(((const float4*)(h + (long long)d * EMB))[lane], W4[32 + lane]);
    if (lane < 16)
        acc += dot4(((const float4*)(e + (long long)warp * EDGE_DIM))[lane],
                    W4[64 + lane]);
#pragma unroll
    for (int off = 16; off; off >>= 1)
        acc += __shfl_down_sync(0xffffffffu, acc, off);
    if (lane == 0) out[warp] = acc + b[0];
}

extern "C" void kernel_launch(void* const* d_in, const int* in_sizes, int n_in,
                              void* d_out, int out_size)
{
    const float* x          = (const float*)d_in[0];
    const float* edge_attr  = (const float*)d_in[1];
    const void*  ei         = (const void*)d_in[2];
    const float* emb_W      = (const float*)d_in[3];
    const float* emb_b      = (const float*)d_in[4];
    const float* msg_W      = (const float*)d_in[5];
    const float* msg_b      = (const float*)d_in[6];
    const float* upd_W      = (const float*)d_in[7];
    const float* upd_b      = (const float*)d_in[8];
    const float* eupd_W     = (const float*)d_in[9];
    const float* eupd_b     = (const float*)d_in[10];
    const float* npred_W    = (const float*)d_in[11];
    const float* npred_b    = (const float*)d_in[12];
    const float* epred_W    = (const float*)d_in[13];
    const float* epred_b    = (const float*)d_in[14];
    float* out = (float*)d_out;

    float *h = nullptr, *aggr = nullptr, *ebuf = nullptr;
    int *src = nullptr, *dst = nullptr;
    cudaGetSymbolAddress((void**)&h, g_h);
    cudaGetSymbolAddress((void**)&aggr, g_aggr);
    cudaGetSymbolAddress((void**)&ebuf, g_e);
    cudaGetSymbolAddress((void**)&src, g_src);
    cudaGetSymbolAddress((void**)&dst, g_dst);

    int nsm = 148;
    cudaDeviceGetAttribute(&nsm, cudaDevAttrMultiProcessorCount, 0);

    cudaFuncSetAttribute(gemm_gather<128>,
                         cudaFuncAttributeMaxDynamicSharedMemorySize, 196608);
    cudaFuncSetAttribute(gemm_gather<64>,
                         cudaFuncAttributeMaxDynamicSharedMemorySize, 147456);
    cudaFuncSetAttribute(gemm_gather<32>,
                         cudaFuncAttributeMaxDynamicSharedMemorySize, 81920);

    // Normalize edge_index (int32 or int64) into int32 g_src/g_dst.
    detect_kernel<<<1, 256>>>((const unsigned int*)ei);
    convert_kernel<<<nsm * 4, 256>>>(ei);

    const int nt_n = (N_NODES + 127) / 128;  // 391 node tiles

    // h = x @ emb_W + emb_b   (no relu)
    gemm_gather<128><<<imin_host(nt_n, nsm), 512,
                       (IN_DIM * 128 + IN_DIM * 128) * 4>>>(
        N_NODES, x, nullptr, IN_DIM, nullptr, nullptr, 0, nullptr, nullptr, 0,
        emb_W, emb_b, h, nullptr, 0);

    for (int l = 0; l < 2; ++l) {
        const float* e_in = (l == 0) ? edge_attr : ebuf;

        zero_kernel<<<nsm * 4, 256>>>((float4*)aggr, N_NODES * EMB / 4);

        // fused message + scatter-sum:
        // aggr[dst] += relu([h[src], e] @ msg_W + msg_b)
        gemm_gather<128><<<nsm, 512, (192 * 128 + 128 * 128) * 4>>>(
            N_EDGES, h, src, EMB, e_in, nullptr, EDGE_DIM, nullptr, nullptr, 0,
            msg_W + l * 192 * 128, msg_b + l * 128, aggr, dst, 1);

        // h = relu([aggr, h] @ upd_W + upd_b)   (in-place safe: per-row dep)
        gemm_gather<128><<<imin_host(nt_n, nsm), 512,
                           (256 * 128 + 128 * 128) * 4>>>(
            N_NODES, aggr, nullptr, EMB, h, nullptr, EMB, nullptr, nullptr, 0,
            upd_W + l * 256 * 128, upd_b + l * 128, h, nullptr, 1);

        // e = relu([h[src], h[dst], e] @ eupd_W + eupd_b)  (in-place safe)
        gemm_gather<64><<<nsm, 512, (320 * 64 + 128 * 128) * 4>>>(
            N_EDGES, h, src, EMB, h, dst, EMB, e_in, nullptr, EDGE_DIM,
            eupd_W + l * 320 * 64, eupd_b + l * 64, ebuf, nullptr, 1);
    }

    // node_pred = h @ npred_W + npred_b
    gemm_gather<32><<<imin_host(nt_n, nsm), 512,
                      (128 * 32 + 128 * 128) * 4>>>(
        N_NODES, h, nullptr, EMB, nullptr, nullptr, 0, nullptr, nullptr, 0,
        npred_W, npred_b, out, nullptr, 0);

    // edge_pred
    edge_pred_kernel<<<(N_EDGES + 7) / 8, 256>>>(
        h, ebuf, src, dst, epred_W, epred_b,
        out + (long long)N_NODES * OUT_DIM, N_EDGES);
}